// round 17
// baseline (speedup 1.0000x reference)
#include <cuda_runtime.h>
#include <cuda_fp16.h>
#include <cstdint>
#include <math.h>

// ---------------------------------------------------------------------------
// Portable tensor-core path: mma.sync + ldmatrix (no sm_103a-gated PTX).
// Round 17: R16 (persistent grid, K-permuted W0, permuted head) +
// software-pipelined weight ldmatrix: double-buffered B fragments, each
// loop's first load hoisted above the preceding repack/convert block.
// ---------------------------------------------------------------------------

#define LDSM_X4(r0, r1, r2, r3, addr) \
    asm volatile("ldmatrix.sync.aligned.m8n8.x4.shared.b16 {%0,%1,%2,%3}, [%4];" \
                 : "=r"(r0), "=r"(r1), "=r"(r2), "=r"(r3) : "r"(addr))

#define LDSM_X2(r0, r1, addr) \
    asm volatile("ldmatrix.sync.aligned.m8n8.x2.shared.b16 {%0,%1}, [%2];" \
                 : "=r"(r0), "=r"(r1) : "r"(addr))

#define MMA16816(c, a0, a1, a2, a3, b0, b1) \
    asm volatile("mma.sync.aligned.m16n8k16.row.col.f32.f16.f16.f32 " \
                 "{%0,%1,%2,%3}, {%4,%5,%6,%7}, {%8,%9}, {%0,%1,%2,%3};" \
                 : "+f"((c)[0]), "+f"((c)[1]), "+f"((c)[2]), "+f"((c)[3]) \
                 : "r"(a0), "r"(a1), "r"(a2), "r"(a3), "r"(b0), "r"(b1))

namespace {

__device__ __forceinline__ uint32_t smem_u32(const void* p) {
    uint32_t a;
    asm("{ .reg .u64 t; cvta.to.shared.u64 t, %1; cvt.u32.u64 %0, t; }"
        : "=r"(a) : "l"(p));
    return a;
}

__device__ __forceinline__ uint32_t pack_f16x2(float lo, float hi) {
    uint32_t r;
    asm("cvt.rn.f16x2.f32 %0, %1, %2;" : "=r"(r) : "f"(hi), "f"(lo));
    return r;
}

__device__ __forceinline__ uint32_t pack_relu2(float lo, float hi) {
    uint32_t r = pack_f16x2(lo, hi);
    asm("max.f16x2 %0, %0, %1;" : "+r"(r) : "r"(0u));
    return r;
}

__device__ __forceinline__ float2 lds64(uint32_t addr) {
    float2 r;
    asm volatile("ld.shared.v2.f32 {%0,%1}, [%2];"
                 : "=f"(r.x), "=f"(r.y) : "r"(addr));
    return r;
}

__device__ __forceinline__ float softplus_dev(float s) {
    return (s > 20.0f) ? s : log1pf(expf(s));
}

constexpr int WSTR = 72;     // halfs per SMEM row (144B) -> ldmatrix conflict-free
constexpr int CTA_THREADS = 128;
constexpr int GRID = 608;    // 152 SMs x 4 CTAs/SM, all resident from wave 1

__global__ void __launch_bounds__(128, 4) ngp_mlp_kernel(
    const float* __restrict__ feat,
    const float* __restrict__ W0, const float* __restrict__ b0,
    const float* __restrict__ W1, const float* __restrict__ b1,
    const float* __restrict__ Ws, const float* __restrict__ bs,
    const float* __restrict__ Wr, const float* __restrict__ br,
    float* __restrict__ sigma_out, float* __restrict__ rgb_out,
    int nchunks)        // total 128-row chunks
{
    __shared__ __half w0t[64 * WSTR];      // [n<64][perm k<32] fp16
    __shared__ __half w1t[64 * WSTR];      // [n<64][k<64]
    __shared__ __half w2t[24 * WSTR];      // permuted head: h<16 rgb, h=16 sigma
    __shared__ float  sbias[152];          // b0 | b1 | permuted head bias

    const int tid  = threadIdx.x;
    const int wid  = tid >> 5;
    const int lane = tid & 31;

    // ---- stage weights: fp32 gmem [K][N] -> fp16 smem [N][K] ----
    // W0: K-permuted so feat can be loaded as contiguous float4.
    for (int i = tid; i < 32 * 64; i += CTA_THREADS) {
        int k = i >> 6, n = i & 63;
        int l = (k & 16) + ((k >> 2) & 3) * 2 + (k & 1) + ((k >> 1) & 1) * 8;
        w0t[n * WSTR + l] = __float2half(W0[i]);
    }
    for (int i = tid; i < 64 * 64; i += CTA_THREADS) {
        int k = i >> 6, n = i & 63;
        w1t[n * WSTR + k] = __float2half(W1[i]);
    }
    for (int i = tid; i < 24 * WSTR; i += CTA_THREADS)
        w2t[i] = __float2half(0.0f);
    if (tid < 64) { sbias[tid] = b0[tid]; sbias[64 + tid] = b1[tid]; }
    if (tid < 24) {
        float v = 0.0f;
        if (tid == 16) v = bs[0] - 1.0f;
        else if (tid < 16) {
            int n = tid >> 3, c = (tid >> 1) & 3, j = tid & 1;
            v = br[4 * c + 2 * n + j];
        }
        sbias[128 + tid] = v;
    }
    __syncthreads();
    if (tid < 64)
        w2t[16 * WSTR + tid] = __float2half(Ws[tid]);   // sigma at head col 16
    for (int i = tid; i < 64 * 16; i += CTA_THREADS) {   // rgb col g -> pos h
        int k = i >> 4, g = i & 15;
        int h = ((g >> 1) & 1) * 8 + (g >> 2) * 2 + (g & 1);
        w2t[h * WSTR + k] = __float2half(Wr[i]);
    }
    __syncthreads();

    // ---- addressing ----
    const uint32_t w0b = smem_u32(w0t), w1b = smem_u32(w1t), w2b = smem_u32(w2t);
    const uint32_t sb  = smem_u32(sbias);
    const int l15  = lane & 15;
    const int col2 = (lane & 3) * 2;
    const int cq   = lane & 3;

    const uint32_t bl4 = (uint32_t)((((lane >> 4) & 1) * 8 + (lane & 7)) * (WSTR * 2)
                                    + ((lane >> 3) & 1) * 16);
    const uint32_t bl2 = (uint32_t)((l15 & 7) * (WSTR * 2) + ((l15 >> 3) & 1) * 16);

    const int ep_row   = lane >> 2;          // A-fragment row within tile

    const uint32_t sb0 = sb + (uint32_t)col2 * 4;        // b0
    const uint32_t sb1 = sb0 + 256;                      // b1
    const uint32_t sbh = sb0 + 512;                      // head

    const float4* f4 = (const float4*)feat;

    int chunk = blockIdx.x;
    if (chunk >= nchunks) return;

    // prime pipeline: contiguous float4 feat loads for first chunk
    float4 vf[2][2][2];
    {
        size_t rb = (size_t)chunk * 128 + (size_t)(wid * 32 + ep_row);
        #pragma unroll
        for (int t = 0; t < 2; t++)
            #pragma unroll
            for (int h = 0; h < 2; h++)
                #pragma unroll
                for (int kt = 0; kt < 2; kt++)
                    vf[t][h][kt] =
                        f4[(rb + (size_t)(t * 16 + h * 8)) * 8 + kt * 4 + cq];
    }

    #pragma unroll 1
    for (; chunk < nchunks; chunk += GRID) {
        const int warp_r0 = chunk * 128 + wid * 32;

        // -- hoisted first B load of layer 0 (covered by convert below) --
        uint32_t bb[2][4];
        LDSM_X4(bb[0][0], bb[0][1], bb[0][2], bb[0][3], w0b + bl4);

        // -- convert prefetched feat to layer-0 A fragments (vf dies here) --
        uint32_t A0[2][2][4];
        #pragma unroll
        for (int t = 0; t < 2; t++)
            #pragma unroll
            for (int kt = 0; kt < 2; kt++)
                #pragma unroll
                for (int h = 0; h < 2; h++) {
                    A0[t][kt][h]     = pack_f16x2(vf[t][h][kt].x, vf[t][h][kt].y);
                    A0[t][kt][2 + h] = pack_f16x2(vf[t][h][kt].z, vf[t][h][kt].w);
                }

        // -- layer 0: [32,32] @ W0(permuted), pipelined B stream --
        float c[2][8][4];
        #pragma unroll
        for (int nt = 0; nt < 8; nt++) {
            float2 bv = lds64(sb0 + (uint32_t)nt * 32);
            #pragma unroll
            for (int t = 0; t < 2; t++) {
                c[t][nt][0] = bv.x; c[t][nt][1] = bv.y;
                c[t][nt][2] = bv.x; c[t][nt][3] = bv.y;
            }
        }
        #pragma unroll
        for (int s = 0; s < 8; s++) {
            const int kt = s >> 2, np = (s & 3) * 2;
            const int cur = s & 1, nxt = cur ^ 1;
            if (s < 7) {
                const int sn = s + 1;
                LDSM_X4(bb[nxt][0], bb[nxt][1], bb[nxt][2], bb[nxt][3],
                        w0b + bl4 + (uint32_t)((sn & 3) * 2) * (8 * WSTR * 2)
                                  + (uint32_t)(sn >> 2) * 32);
            }
            MMA16816(c[0][np],     A0[0][kt][0], A0[0][kt][1],
                     A0[0][kt][2], A0[0][kt][3], bb[cur][0], bb[cur][1]);
            MMA16816(c[0][np + 1], A0[0][kt][0], A0[0][kt][1],
                     A0[0][kt][2], A0[0][kt][3], bb[cur][2], bb[cur][3]);
            MMA16816(c[1][np],     A0[1][kt][0], A0[1][kt][1],
                     A0[1][kt][2], A0[1][kt][3], bb[cur][0], bb[cur][1]);
            MMA16816(c[1][np + 1], A0[1][kt][0], A0[1][kt][1],
                     A0[1][kt][2], A0[1][kt][3], bb[cur][2], bb[cur][3]);
        }

        // -- hoisted first B load of layer 1 (covered by repack below) --
        LDSM_X4(bb[0][0], bb[0][1], bb[0][2], bb[0][3], w1b + bl4);

        // -- repack C -> A (relu fused) --
        uint32_t A1[2][4][4];
        #pragma unroll
        for (int t = 0; t < 2; t++)
            #pragma unroll
            for (int kt = 0; kt < 4; kt++) {
                A1[t][kt][0] = pack_relu2(c[t][2 * kt][0],     c[t][2 * kt][1]);
                A1[t][kt][1] = pack_relu2(c[t][2 * kt][2],     c[t][2 * kt][3]);
                A1[t][kt][2] = pack_relu2(c[t][2 * kt + 1][0], c[t][2 * kt + 1][1]);
                A1[t][kt][3] = pack_relu2(c[t][2 * kt + 1][2], c[t][2 * kt + 1][3]);
            }

        // -- layer 1: [32,64] @ W1, pipelined B stream --
        #pragma unroll
        for (int nt = 0; nt < 8; nt++) {
            float2 bv = lds64(sb1 + (uint32_t)nt * 32);
            #pragma unroll
            for (int t = 0; t < 2; t++) {
                c[t][nt][0] = bv.x; c[t][nt][1] = bv.y;
                c[t][nt][2] = bv.x; c[t][nt][3] = bv.y;
            }
        }
        #pragma unroll
        for (int s = 0; s < 16; s++) {
            const int kt = s >> 2, np = (s & 3) * 2;
            const int cur = s & 1, nxt = cur ^ 1;
            if (s < 15) {
                const int sn = s + 1;
                LDSM_X4(bb[nxt][0], bb[nxt][1], bb[nxt][2], bb[nxt][3],
                        w1b + bl4 + (uint32_t)((sn & 3) * 2) * (8 * WSTR * 2)
                                  + (uint32_t)(sn >> 2) * 32);
            }
            MMA16816(c[0][np],     A1[0][kt][0], A1[0][kt][1],
                     A1[0][kt][2], A1[0][kt][3], bb[cur][0], bb[cur][1]);
            MMA16816(c[0][np + 1], A1[0][kt][0], A1[0][kt][1],
                     A1[0][kt][2], A1[0][kt][3], bb[cur][2], bb[cur][3]);
            MMA16816(c[1][np],     A1[1][kt][0], A1[1][kt][1],
                     A1[1][kt][2], A1[1][kt][3], bb[cur][0], bb[cur][1]);
            MMA16816(c[1][np + 1], A1[1][kt][0], A1[1][kt][1],
                     A1[1][kt][2], A1[1][kt][3], bb[cur][2], bb[cur][3]);
        }

        // -- LATE prefetch of next chunk's feat (vf live only from here) --
        {
            const int cn = (chunk + GRID < nchunks) ? chunk + GRID : chunk;
            size_t rb = (size_t)cn * 128 + (size_t)(wid * 32 + ep_row);
            #pragma unroll
            for (int t = 0; t < 2; t++)
                #pragma unroll
                for (int h = 0; h < 2; h++)
                    #pragma unroll
                    for (int kt = 0; kt < 2; kt++)
                        vf[t][h][kt] =
                            f4[(rb + (size_t)(t * 16 + h * 8)) * 8 + kt * 4 + cq];
        }

        // -- hoisted first B loads of head (covered by repack below) --
        uint32_t hb[2][6];
        LDSM_X4(hb[0][0], hb[0][1], hb[0][2], hb[0][3], w2b + bl4);
        LDSM_X2(hb[0][4], hb[0][5], w2b + bl2 + (uint32_t)(16 * WSTR * 2));

        // -- repack again (reuse A1 storage) --
        #pragma unroll
        for (int t = 0; t < 2; t++)
            #pragma unroll
            for (int kt = 0; kt < 4; kt++) {
                A1[t][kt][0] = pack_relu2(c[t][2 * kt][0],     c[t][2 * kt][1]);
                A1[t][kt][1] = pack_relu2(c[t][2 * kt][2],     c[t][2 * kt][3]);
                A1[t][kt][2] = pack_relu2(c[t][2 * kt + 1][0], c[t][2 * kt + 1][1]);
                A1[t][kt][3] = pack_relu2(c[t][2 * kt + 1][2], c[t][2 * kt + 1][3]);
            }

        // -- heads (permuted), pipelined B stream --
        float ch[2][3][4];
        #pragma unroll
        for (int nt = 0; nt < 3; nt++) {
            float2 bv = lds64(sbh + (uint32_t)nt * 32);
            #pragma unroll
            for (int t = 0; t < 2; t++) {
                ch[t][nt][0] = bv.x; ch[t][nt][1] = bv.y;
                ch[t][nt][2] = bv.x; ch[t][nt][3] = bv.y;
            }
        }
        #pragma unroll
        for (int kt = 0; kt < 4; kt++) {
            const int cur = kt & 1, nxt = cur ^ 1;
            if (kt < 3) {
                LDSM_X4(hb[nxt][0], hb[nxt][1], hb[nxt][2], hb[nxt][3],
                        w2b + bl4 + (uint32_t)(kt + 1) * 32);
                LDSM_X2(hb[nxt][4], hb[nxt][5],
                        w2b + bl2 + (uint32_t)(16 * WSTR * 2)
                                  + (uint32_t)(kt + 1) * 32);
            }
            #pragma unroll
            for (int t = 0; t < 2; t++) {
                MMA16816(ch[t][0], A1[t][kt][0], A1[t][kt][1],
                         A1[t][kt][2], A1[t][kt][3], hb[cur][0], hb[cur][1]);
                MMA16816(ch[t][1], A1[t][kt][0], A1[t][kt][1],
                         A1[t][kt][2], A1[t][kt][3], hb[cur][2], hb[cur][3]);
                MMA16816(ch[t][2], A1[t][kt][0], A1[t][kt][1],
                         A1[t][kt][2], A1[t][kt][3], hb[cur][4], hb[cur][5]);
            }
        }

        // -- epilogue: fully coalesced stores --
        #pragma unroll
        for (int t = 0; t < 2; t++) {
            const int gr0 = warp_r0 + t * 16 + ep_row;
            const int gr1 = gr0 + 8;
            *(float4*)(rgb_out + (size_t)gr0 * 16 + 4 * cq) =
                make_float4(ch[t][0][0], ch[t][0][1], ch[t][1][0], ch[t][1][1]);
            *(float4*)(rgb_out + (size_t)gr1 * 16 + 4 * cq) =
                make_float4(ch[t][0][2], ch[t][0][3], ch[t][1][2], ch[t][1][3]);
            if (cq == 0) {
                sigma_out[gr0] = softplus_dev(ch[t][2][0]);
                sigma_out[gr1] = softplus_dev(ch[t][2][2]);
            }
        }
    }
}

}  // namespace

extern "C" void kernel_launch(void* const* d_in, const int* in_sizes, int n_in,
                              void* d_out, int out_size) {
    const float* feat = (const float*)d_in[0];
    const float* W0   = (const float*)d_in[1];
    const float* b0   = (const float*)d_in[2];
    const float* W1   = (const float*)d_in[3];
    const float* b1   = (const float*)d_in[4];
    const float* Ws   = (const float*)d_in[5];
    const float* bs   = (const float*)d_in[6];
    const float* Wr   = (const float*)d_in[7];
    const float* br   = (const float*)d_in[8];

    float* out = (float*)d_out;
    const int Bn = in_sizes[0] / 32;           // rows (2^21)
    float* sigma = out;                         // [B]
    float* rgb   = out + Bn;                    // [B,16]

    const int nchunks = Bn / 128;               // 16384
    const int grid = (nchunks < GRID) ? nchunks : GRID;
    ngp_mlp_kernel<<<grid, CTA_THREADS>>>(feat, W0, b0, W1, b1, Ws, bs, Wr, br,
                                          sigma, rgb, nchunks);
}